// round 13
// baseline (speedup 1.0000x reference)
#include <cuda_runtime.h>
#include <cstdint>

// HH_Synaptic, Round 13: LUT gates (affine x' = c1(V)x + c0(V), 4096-bin
// smem table, linear interp) + 2 half-filled warps per SMSP (sibling warp
// covers LDS/spine latency; regime is issue-bound, LUT minimizes issue count)
// + pipelined output store. 128 blocks x 256 threads, lanes >= 16 idle.

#define N_DIM 2000
#define L_DIM 1024
#define PF    4
#define BINS  4096
#define VLO   (-128.0f)
#define VRANGE 192.0f
#define DELTA (VRANGE / BINS)
#define INVD  (BINS / VRANGE)
#define TAB_BYTES (BINS * 48)

__device__ __forceinline__ float ex2f_(float x){ float r; asm("ex2.approx.f32 %0, %1;" : "=f"(r) : "f"(x)); return r; }
__device__ __forceinline__ float rcpf_(float x){ float r; asm("rcp.approx.f32 %0, %1;" : "=f"(r) : "f"(x)); return r; }

// accurate affine gate coefficients at a table node (build-time only)
__device__ void node_coeffs(float V, float* c) {
    float dv25 = V - 25.0f, dv35 = V + 35.0f;
    float aN, bN, aM, bM;
    if (dv25 == 0.0f) { aN = 0.18f;  bN = 0.018f; }     // analytic limits (smooth table)
    else {
        aN =  0.02f  * dv25 / (1.0f - expf(-dv25 / 9.0f));
        bN = -0.002f * dv25 / (1.0f - expf( dv25 / 9.0f));
    }
    if (dv35 == 0.0f) { aM = 1.638f; bM = 1.116f; }
    else {
        aM =  0.182f * dv35 / (1.0f - expf(-dv35 / 9.0f));
        bM = -0.124f * dv35 / (1.0f - expf( dv35 / 9.0f));
    }
    float aH = 0.25f * expf((-V - 90.0f) / 12.0f);
    float bH = 0.25f * expf(( V + 34.0f) / 12.0f);
    float pN = 0.01f * (aN + bN);
    float pM = 0.01f * (aM + bM);
    float pH = 0.01f * (aH + bH);
    c[0] = 0.02f * aN / (1.0f + pN);  c[1] = (1.0f - pN) / (1.0f + pN);
    c[2] = 0.02f * aM / (1.0f + pM);  c[3] = (1.0f - pM) / (1.0f + pM);
    c[4] = 0.02f * aH / (1.0f + pH);  c[5] = (1.0f - pH) / (1.0f + pH);
}

__global__ __launch_bounds__(256, 1)
void hh_synaptic_kernel(const float* __restrict__ z, float* __restrict__ out) {
    extern __shared__ float4 tab[];   // per bin: [A={cn0,cn1,cm0,cm1}, dA, {ch0,ch1,dh0,dh1}]

    // ---- build LUT (all 256 threads, 16 bins each) ----
    for (int i = threadIdx.x; i < BINS; i += blockDim.x) {
        float c0[6], c1[6];
        float Vn0 = VLO + (float)i * DELTA;
        node_coeffs(Vn0, c0);
        node_coeffs(Vn0 + DELTA, c1);
        float4 A, D, H;
        A.x = c0[0]; A.y = c0[1]; A.z = c0[2]; A.w = c0[3];
        D.x = c1[0]-c0[0]; D.y = c1[1]-c0[1]; D.z = c1[2]-c0[2]; D.w = c1[3]-c0[3];
        H.x = c0[4]; H.y = c0[5]; H.z = c1[4]-c0[4]; H.w = c1[5]-c0[5];
        tab[i*3+0] = A; tab[i*3+1] = D; tab[i*3+2] = H;
    }
    __syncthreads();

    const int lane = threadIdx.x & 31;
    if (lane >= 16) return;                         // half-filled warps: 2/SMSP
    const int warp  = (blockIdx.x * blockDim.x + threadIdx.x) >> 5;  // 0..1023
    const int chain = warp * 16 + lane;             // 0..16383
    const int b = chain >> 10;
    const int l = chain & (L_DIM - 1);

    const float* zp = z   + (size_t)b * (N_DIM * L_DIM) + l;
    float*       op = out + (size_t)b * (N_DIM * L_DIM) + l;

    const float LOG2E = 1.4426950408889634f;
    const float cSIG  = LOG2E / 3.0f;

    // Reference's exact-equality patch constants (V==25 -> n, V==-35 -> m)
    const float pN_ = 0.01f*(0.18f+0.08f),  pM_ = 0.01f*(1.638f+1.16f);
    const float kNp = (1.0f-pN_)/(1.0f+pN_), cNp = (0.02f*0.18f)/(1.0f+pN_);
    const float kMp = (1.0f-pM_)/(1.0f+pM_), cMp = (0.02f*1.638f)/(1.0f+pM_);

    // State
    float V = -70.0f;
    float m = 0.0f, n = 0.0f, h = 1.0f, y = 0.0f;
    float yG  = 1.003f;      // 1.003 + 0.01*y (staged)
    float h40 = 40.0f;       // 40*h (staged)

    // Pipelined output: row 0 stored at head of first iteration
    float argS_prev = -(V + 20.0f) * cSIG;
    float* olPrev = op;

    // z prefetch ring: step k consumes z index (k-1)
    float zbuf[PF];
    #pragma unroll
    for (int j = 0; j < PF; ++j)
        zbuf[j] = __ldg(zp + (size_t)j * L_DIM);

    #pragma unroll 4
    for (int k = 1; k < N_DIM; ++k) {
        float zc = zbuf[0];
        #pragma unroll
        for (int j = 0; j < PF - 1; ++j) zbuf[j] = zbuf[j + 1];
        int pidx = min(k - 1 + PF, N_DIM - 1);
        zbuf[PF - 1] = __ldg(zp + (size_t)pidx * L_DIM);

        // ---- head: pow chain -> Gp -> rcp ----
        float mm   = m * m;
        float mh   = m * h40;
        float pow1 = mm * mh;                        // GNA*m^3*h
        float n2   = n * n;
        float n35  = 35.0f * n2;
        float pow2 = n2 * n35;                       // GK*n^4
        float psum = pow1 + pow2;
        float Gp   = fmaf(0.01f, psum, yG);          // 1 + G
        float r    = rcpf_(Gp);

        // ---- rcp shadow: previous step's output sigmoid + store ----
        float eS   = ex2f_(argS_prev);
        float outP = rcpf_(1.0f + eS);
        *olPrev = outP;
        olPrev += L_DIM;

        // ---- rcp shadow: y-rail (series rcp, pY <= 0.011) ----
        float pY = fmaf(0.01f, zc, 0.001f);
        float rY = fmaf(pY, fmaf(pY, 1.0f - pY, -1.0f), 1.0f);
        float yn = fmaf(zc, 0.02f, fmaf(-pY, y, y)) * rY;

        // ---- E / num (parallel with rcp) ----
        float E    = fmaf(pow1, 55.0f, fmaf(pow2, -77.0f, -19.5f));
        float b2   = fmaf(0.02f, E, fmaf(2.0f, V, 0.02f));
        float num  = fmaf(-V, Gp, b2);
        float numi = num * INVD;
        float numS = num * (-cSIG);

        // ---- consume r: Vn, table index, next sigmoid arg ----
        float Vn  = num * r;
        float t   = fmaf(numi, r, -VLO * INVD);
        argS_prev = fmaf(numS, r, -20.0f * cSIG);
        t = fminf(fmaxf(t, 0.5f), (float)BINS - 1.5f);

        // float-trick nearest-int split (no F2I/I2F)
        float s    = t + 8388608.0f;                 // 2^23
        float fl   = s - 8388608.0f;
        float frac = t - fl;                         // [-0.5, 0.5]
        uint32_t bi = __float_as_uint(s) & 0x7FFFFFu;

        const float4* bp = &tab[bi * 3];
        float4 A  = bp[0];
        float4 Dl = bp[1];
        float4 Hc = bp[2];

        float cn0 = fmaf(frac, Dl.x, A.x);
        float cn1 = fmaf(frac, Dl.y, A.y);
        float cm0 = fmaf(frac, Dl.z, A.z);
        float cm1 = fmaf(frac, Dl.w, A.w);
        float ch0 = fmaf(frac, Hc.z, Hc.x);
        float ch1 = fmaf(frac, Hc.w, Hc.y);

        // reference's exact-equality singularity patches
        bool sN = (Vn == 25.0f);
        bool sM = (Vn == -35.0f);
        cn0 = sN ? cNp : cn0;  cn1 = sN ? kNp : cn1;
        cm0 = sM ? cMp : cm0;  cm1 = sM ? kMp : cm1;

        // ---- affine gate updates ----
        n = fmaf(cn1, n, cn0);
        m = fmaf(cm1, m, cm0);
        h = fmaf(ch1, h, ch0);
        y = yn;
        V = Vn;

        // stage off-spine values for next step
        h40 = 40.0f * h;
        yG  = fmaf(0.01f, yn, 1.003f);
    }

    // drain the pipelined output (row N_DIM-1)
    {
        float eS = ex2f_(argS_prev);
        *olPrev = rcpf_(1.0f + eS);
    }
}

extern "C" void kernel_launch(void* const* d_in, const int* in_sizes, int n_in,
                              void* d_out, int out_size) {
    const float* z = (const float*)d_in[0];
    float* out = (float*)d_out;
    cudaFuncSetAttribute(hh_synaptic_kernel,
                         cudaFuncAttributeMaxDynamicSharedMemorySize, TAB_BYTES);
    // 1024 half-filled warps: 128 blocks x 256 threads -> 2 warps/SMSP
    hh_synaptic_kernel<<<128, 256, TAB_BYTES>>>(z, out);
}

// round 14
// speedup vs baseline: 1.0887x; 1.0887x over previous
#include <cuda_runtime.h>

// HH_Synaptic, Round 14: R11 scaffold + factored rail denominators.
// D+q = e*P + Q and D-q = e*P2 + Q2 with P,Q,P2,Q2,R precomputed from dv
// inside the ex2 shadow -> rail rcp issues 1 FMA after ex2 lands (was 2-3).
// Solo warp per SMSP (co-residency proven unable to compress per-warp time).

#define N_DIM 2000
#define L_DIM 1024
#define PF    4

__device__ __forceinline__ float ex2f_(float x){ float r; asm("ex2.approx.f32 %0, %1;" : "=f"(r) : "f"(x)); return r; }
__device__ __forceinline__ float rcpf_(float x){ float r; asm("rcp.approx.f32 %0, %1;" : "=f"(r) : "f"(x)); return r; }

__global__ __launch_bounds__(128, 1)
void hh_synaptic_kernel(const float* __restrict__ z, float* __restrict__ out) {
    const int idx = blockIdx.x * blockDim.x + threadIdx.x;   // 0 .. 16383
    const int b = idx >> 10;
    const int l = idx & (L_DIM - 1);

    const float* zp = z   + (size_t)b * (N_DIM * L_DIM) + l;
    float*       op = out + (size_t)b * (N_DIM * L_DIM) + l;

    const float LOG2E = 1.4426950408889634f;
    const float c9    = LOG2E / 9.0f;
    const float c12   = LOG2E / 12.0f;
    const float cSIG  = LOG2E / 3.0f;
    const float cAH01 = 0.01f * 0.25f * expf(-56.0f / 12.0f);

    // Rail constants: N: s=0.02, t=0.002 ; M: s=0.182, t=0.124
    const float sN01 = 2.0e-4f,  tN01 = 2.0e-5f,  RN = 4.0e-4f;    // 0.01s, 0.01t, 0.02s
    const float sM01 = 1.82e-3f, tM01 = 1.24e-3f, RM = 3.64e-3f;

    // Singularity-patch constants (reference's exact-equality cases): x' = k*x + c
    const float pN_ = 0.01f*(0.18f+0.08f),  pM_ = 0.01f*(1.638f+1.16f);
    const float kNp = (1.0f-pN_)/(1.0f+pN_), cNp = (0.02f*0.18f)/(1.0f+pN_);
    const float kMp = (1.0f-pM_)/(1.0f+pM_), cMp = (0.02f*1.638f)/(1.0f+pM_);

    // State
    float V = -70.0f;
    float m = 0.0f, n = 0.0f, h = 1.0f, y = 0.0f;
    float yG  = 1.003f;          // 1.003 + 0.01*y   (staged off-spine)
    float h40 = 40.0f;           // 40*h             (staged off-spine)

    // Pipelined output: argS for row 0 stores at head of first iteration
    float argS_prev = -(V + 20.0f) * cSIG;
    float* olPrev = op;

    // z prefetch ring: step k consumes z index (k-1)
    float zbuf[PF];
    #pragma unroll
    for (int j = 0; j < PF; ++j)
        zbuf[j] = __ldg(zp + (size_t)j * L_DIM);

    #pragma unroll 4
    for (int k = 1; k < N_DIM; ++k) {
        float zc = zbuf[0];
        #pragma unroll
        for (int j = 0; j < PF - 1; ++j) zbuf[j] = zbuf[j + 1];
        int pidx = min(k - 1 + PF, N_DIM - 1);
        zbuf[PF - 1] = __ldg(zp + (size_t)pidx * L_DIM);

        // ---- head: pow chain -> Gp -> rcp ----
        float mm   = m * m;
        float mh   = m * h40;
        float pow1 = mm * mh;                            // GNA*m^3*h
        float n2   = n * n;
        float n35  = 35.0f * n2;
        float pow2 = n2 * n35;                           // GK*n^4
        float psum = pow1 + pow2;
        float Gp   = fmaf(0.01f, psum, yG);              // 1 + G
        float r    = rcpf_(Gp);

        // ---- rcp shadow: previous step's output sigmoid + store ----
        float eS   = ex2f_(argS_prev);
        float outP = rcpf_(1.0f + eS);
        *olPrev = outP;
        olPrev += L_DIM;

        // ---- rcp shadow: y-rail (V-independent), series rcp, pY <= 0.011 ----
        float pY = fmaf(0.01f, zc, 0.001f);
        float rY = fmaf(pY, fmaf(pY, 1.0f - pY, -1.0f), 1.0f);
        float yn = fmaf(zc, 0.02f, fmaf(-pY, y, y)) * rY;

        // ---- E / num (parallel with rcp) ----
        float E    = fmaf(pow1, 55.0f, fmaf(pow2, -77.0f, -19.5f));
        float b2   = fmaf(0.02f, E, fmaf(2.0f, V, 0.02f));
        float num  = fmaf(-V, Gp, b2);
        float num9 = num * c9;
        float num12 = num * c12;
        float numS  = num * (-cSIG);

        // ---- consume r: Vn, dv, ex2 args ----
        float Vn   = num * r;
        float dv25 = fmaf(num,  r, -25.0f);
        float dv35 = fmaf(num,  r,  35.0f);
        float argN = fmaf(num9, r, -25.0f * c9);
        float argM = fmaf(num9, r,  35.0f * c9);
        float argH = fmaf(num12, r, 34.0f * c12);
        argS_prev  = fmaf(numS, r, -20.0f * cSIG);

        float eN = ex2f_(argN);
        float eM = ex2f_(argM);
        float eH = ex2f_(argH);

        // ---- ex2 shadow: P/Q factors from dv (D+q = e*P + Q, D-q = e*P2 + Q2) ----
        float PN  = fmaf( sN01, dv25, 1.0f);
        float QN  = fmaf( tN01, dv25, -1.0f);
        float P2N = fmaf(-sN01, dv25, 1.0f);
        float Q2N = fmaf(-tN01, dv25, -1.0f);
        float RNe = RN * dv25;                           // 0.02*s*dv
        float PM  = fmaf( sM01, dv35, 1.0f);
        float QM  = fmaf( tM01, dv35, -1.0f);
        float P2M = fmaf(-sM01, dv35, 1.0f);
        float Q2M = fmaf(-tM01, dv35, -1.0f);
        float RMe = RM * dv35;
        float ehc = eH + cAH01;
        float emc = eH - cAH01;

        // ---- rails: one FMA then rcp; numerator hides under the rcp ----
        float dpqN = fmaf(eN, PN, QN);                   // D + q
        float dpqM = fmaf(eM, PM, QM);
        float tH2  = eH * eH;
        float rrN  = rcpf_(dpqN);
        float rrM  = rcpf_(dpqM);
        float denH = fmaf(0.0025f, tH2, ehc);
        float rrH  = rcpf_(denH);
        float dmqN = fmaf(eN, P2N, Q2N);                 // D - q
        float dmqM = fmaf(eM, P2M, Q2M);
        float wH   = fmaf(-0.0025f, tH2, emc);
        float nmN  = fmaf(n, dmqN, RNe * eN);
        float nmM  = fmaf(m, dmqM, RMe * eM);
        float nmH  = fmaf(h, wH, 2.0f * cAH01);
        float resN = nmN * rrN;
        float resM = nmM * rrM;
        float resH = nmH * rrH;

        // reference's exact-equality singularity patches
        n = (dv25 == 0.0f) ? fmaf(n, kNp, cNp) : resN;
        m = (dv35 == 0.0f) ? fmaf(m, kMp, cMp) : resM;
        h = resH;
        y = yn;
        V = Vn;

        // stage off-spine values for next step
        h40 = 40.0f * h;
        yG  = fmaf(0.01f, yn, 1.003f);
    }

    // drain the pipelined output (row N_DIM-1)
    {
        float eS = ex2f_(argS_prev);
        *olPrev = rcpf_(1.0f + eS);
    }
}

extern "C" void kernel_launch(void* const* d_in, const int* in_sizes, int n_in,
                              void* d_out, int out_size) {
    const float* z = (const float*)d_in[0];
    float* out = (float*)d_out;
    hh_synaptic_kernel<<<128, 128>>>(z, out);
}

// round 15
// speedup vs baseline: 1.1411x; 1.0481x over previous
#include <cuda_runtime.h>

// HH_Synaptic, Round 15: R14 body, but the spine's rcp(1+G) is replaced by a
// 2x Newton refinement (4 FMA, 16 cyc) seeded from the PREVIOUS step's exact
// MUFU reciprocal; the exact rcp is recomputed off-spine each step to reseed.
// Gp changes <= ~3%/step -> Newton^2 error ~delta^4 <= 1e-6 relative.
// Tests the hypothesis that dependent-MUFU stages dominate the spine cost.

#define N_DIM 2000
#define L_DIM 1024
#define PF    4

__device__ __forceinline__ float ex2f_(float x){ float r; asm("ex2.approx.f32 %0, %1;" : "=f"(r) : "f"(x)); return r; }
__device__ __forceinline__ float rcpf_(float x){ float r; asm("rcp.approx.f32 %0, %1;" : "=f"(r) : "f"(x)); return r; }

__global__ __launch_bounds__(128, 1)
void hh_synaptic_kernel(const float* __restrict__ z, float* __restrict__ out) {
    const int idx = blockIdx.x * blockDim.x + threadIdx.x;   // 0 .. 16383
    const int b = idx >> 10;
    const int l = idx & (L_DIM - 1);

    const float* zp = z   + (size_t)b * (N_DIM * L_DIM) + l;
    float*       op = out + (size_t)b * (N_DIM * L_DIM) + l;

    const float LOG2E = 1.4426950408889634f;
    const float c9    = LOG2E / 9.0f;
    const float c12   = LOG2E / 12.0f;
    const float cSIG  = LOG2E / 3.0f;
    const float cAH01 = 0.01f * 0.25f * expf(-56.0f / 12.0f);

    // Rail constants: N: s=0.02, t=0.002 ; M: s=0.182, t=0.124
    const float sN01 = 2.0e-4f,  tN01 = 2.0e-5f,  RN = 4.0e-4f;    // 0.01s, 0.01t, 0.02s
    const float sM01 = 1.82e-3f, tM01 = 1.24e-3f, RM = 3.64e-3f;

    // Singularity-patch constants (reference's exact-equality cases): x' = k*x + c
    const float pN_ = 0.01f*(0.18f+0.08f),  pM_ = 0.01f*(1.638f+1.16f);
    const float kNp = (1.0f-pN_)/(1.0f+pN_), cNp = (0.02f*0.18f)/(1.0f+pN_);
    const float kMp = (1.0f-pM_)/(1.0f+pM_), cMp = (0.02f*1.638f)/(1.0f+pM_);

    // State
    float V = -70.0f;
    float m = 0.0f, n = 0.0f, h = 1.0f, y = 0.0f;
    float yG  = 1.003f;          // 1.003 + 0.01*y   (staged off-spine)
    float h40 = 40.0f;           // 40*h             (staged off-spine)

    // Reciprocal seed: first step's Gp is exactly 1.003 (pow1=pow2=0, y=0)
    float rP = rcpf_(1.003f);

    // Pipelined output: argS for row 0 stores at head of first iteration
    float argS_prev = -(V + 20.0f) * cSIG;
    float* olPrev = op;

    // z prefetch ring: step k consumes z index (k-1)
    float zbuf[PF];
    #pragma unroll
    for (int j = 0; j < PF; ++j)
        zbuf[j] = __ldg(zp + (size_t)j * L_DIM);

    #pragma unroll 4
    for (int k = 1; k < N_DIM; ++k) {
        float zc = zbuf[0];
        #pragma unroll
        for (int j = 0; j < PF - 1; ++j) zbuf[j] = zbuf[j + 1];
        int pidx = min(k - 1 + PF, N_DIM - 1);
        zbuf[PF - 1] = __ldg(zp + (size_t)pidx * L_DIM);

        // ---- head: pow chain -> Gp ----
        float mm   = m * m;
        float mh   = m * h40;
        float pow1 = mm * mh;                            // GNA*m^3*h
        float n2   = n * n;
        float n35  = 35.0f * n2;
        float pow2 = n2 * n35;                           // GK*n^4
        float psum = pow1 + pow2;
        float Gp   = fmaf(0.01f, psum, yG);              // 1 + G

        // ---- SPINE: r by 2x Newton from previous step's exact reciprocal ----
        float u1 = fmaf(-Gp, rP, 2.0f);
        float r1 = rP * u1;
        float u2 = fmaf(-Gp, r1, 2.0f);
        float r  = r1 * u2;                              // rel err ~ (dGp/Gp)^4 <= 1e-6

        // ---- off-spine: exact MUFU reciprocal reseeds next step ----
        rP = rcpf_(Gp);

        // ---- shadow: previous step's output sigmoid + store ----
        float eS   = ex2f_(argS_prev);
        float outP = rcpf_(1.0f + eS);
        *olPrev = outP;
        olPrev += L_DIM;

        // ---- shadow: y-rail (V-independent), series rcp, pY <= 0.011 ----
        float pY = fmaf(0.01f, zc, 0.001f);
        float rY = fmaf(pY, fmaf(pY, 1.0f - pY, -1.0f), 1.0f);
        float yn = fmaf(zc, 0.02f, fmaf(-pY, y, y)) * rY;

        // ---- E / num (parallel with the Newton chain) ----
        float E    = fmaf(pow1, 55.0f, fmaf(pow2, -77.0f, -19.5f));
        float b2   = fmaf(0.02f, E, fmaf(2.0f, V, 0.02f));
        float num  = fmaf(-V, Gp, b2);
        float num9 = num * c9;
        float num12 = num * c12;
        float numS  = num * (-cSIG);

        // ---- consume r: Vn, dv, ex2 args ----
        float Vn   = num * r;
        float dv25 = fmaf(num,  r, -25.0f);
        float dv35 = fmaf(num,  r,  35.0f);
        float argN = fmaf(num9, r, -25.0f * c9);
        float argM = fmaf(num9, r,  35.0f * c9);
        float argH = fmaf(num12, r, 34.0f * c12);
        argS_prev  = fmaf(numS, r, -20.0f * cSIG);

        float eN = ex2f_(argN);
        float eM = ex2f_(argM);
        float eH = ex2f_(argH);

        // ---- ex2 shadow: P/Q factors from dv (D+q = e*P + Q, D-q = e*P2 + Q2) ----
        float PN  = fmaf( sN01, dv25, 1.0f);
        float QN  = fmaf( tN01, dv25, -1.0f);
        float P2N = fmaf(-sN01, dv25, 1.0f);
        float Q2N = fmaf(-tN01, dv25, -1.0f);
        float RNe = RN * dv25;                           // 0.02*s*dv
        float PM  = fmaf( sM01, dv35, 1.0f);
        float QM  = fmaf( tM01, dv35, -1.0f);
        float P2M = fmaf(-sM01, dv35, 1.0f);
        float Q2M = fmaf(-tM01, dv35, -1.0f);
        float RMe = RM * dv35;
        float ehc = eH + cAH01;
        float emc = eH - cAH01;

        // ---- rails: one FMA then rcp; numerator hides under the rcp ----
        float dpqN = fmaf(eN, PN, QN);                   // D + q
        float dpqM = fmaf(eM, PM, QM);
        float tH2  = eH * eH;
        float rrN  = rcpf_(dpqN);
        float rrM  = rcpf_(dpqM);
        float denH = fmaf(0.0025f, tH2, ehc);
        float rrH  = rcpf_(denH);
        float dmqN = fmaf(eN, P2N, Q2N);                 // D - q
        float dmqM = fmaf(eM, P2M, Q2M);
        float wH   = fmaf(-0.0025f, tH2, emc);
        float nmN  = fmaf(n, dmqN, RNe * eN);
        float nmM  = fmaf(m, dmqM, RMe * eM);
        float nmH  = fmaf(h, wH, 2.0f * cAH01);
        float resN = nmN * rrN;
        float resM = nmM * rrM;
        float resH = nmH * rrH;

        // reference's exact-equality singularity patches
        n = (dv25 == 0.0f) ? fmaf(n, kNp, cNp) : resN;
        m = (dv35 == 0.0f) ? fmaf(m, kMp, cMp) : resM;
        h = resH;
        y = yn;
        V = Vn;

        // stage off-spine values for next step
        h40 = 40.0f * h;
        yG  = fmaf(0.01f, yn, 1.003f);
    }

    // drain the pipelined output (row N_DIM-1)
    {
        float eS = ex2f_(argS_prev);
        *olPrev = rcpf_(1.0f + eS);
    }
}

extern "C" void kernel_launch(void* const* d_in, const int* in_sizes, int n_in,
                              void* d_out, int out_size) {
    const float* z = (const float*)d_in[0];
    float* out = (float*)d_out;
    hh_synaptic_kernel<<<128, 128>>>(z, out);
}